// round 3
// baseline (speedup 1.0000x reference)
#include <cuda_runtime.h>

#define B_   16
#define T_   48
#define N_   500
#define D_   64
#define SP   68          // padded row stride (floats) for Q/K/V/O/T tiles
#define SP4  17          // SP/4
#define SMEM_FLOATS (T_*128 + 3*T_*SP)
#define SMEM_BYTES  (SMEM_FLOATS*4)

__global__ __launch_bounds__(256, 3)
void fused_temporal_attn(const float* __restrict__ X,  const float* __restrict__ STE,
                         const float* __restrict__ W12, const float* __restrict__ b12,
                         const float* __restrict__ W13, const float* __restrict__ b13,
                         const float* __restrict__ W14, const float* __restrict__ b14,
                         const float* __restrict__ W15, const float* __restrict__ b15,
                         const float* __restrict__ W16, const float* __restrict__ b16,
                         float* __restrict__ out)
{
    extern __shared__ float smem[];
    float* sH = smem;             // [48][128]  (24 KB)
    float* sQ = sH + T_*128;      // [48][SP]
    float* sK = sQ + T_*SP;
    float* sV = sK + T_*SP;
    float* sO = sH;               // alias: attention output, [48][SP] fits in sH
    float* sT = sQ;               // alias: mid output, [48][SP]

    const int tid = threadIdx.x;
    const int n = blockIdx.x;
    const int b = blockIdx.y;

    // ---------------- Phase 0: stage H = [X | STE] ----------------
    {
        const float4* X4 = reinterpret_cast<const float4*>(X);
        const float4* S4 = reinterpret_cast<const float4*>(STE);
        float4* sH4 = reinterpret_cast<float4*>(sH);
        const int base    = (b*T_*N_ + n) * (D_/4);
        const int tstride = N_ * (D_/4);
        #pragma unroll
        for (int idx = tid; idx < T_*16; idx += 256) {
            const int t = idx >> 4, j4 = idx & 15;
            const int g = base + t*tstride + j4;
            sH4[t*32 + j4]      = X4[g];
            sH4[t*32 + 16 + j4] = S4[g];
        }
    }
    __syncthreads();

    // ---------------- Phase 1: q,k,v = relu(H @ W + b) ----------------
    {
        const int j  = tid & 63;
        const int g  = tid >> 6;   // 0..3
        const int t0 = g * 12;
        float aq[12], ak[12], av[12];
        const float bq = __ldg(b12+j), bk = __ldg(b13+j), bv = __ldg(b14+j);
        #pragma unroll
        for (int i = 0; i < 12; i++) { aq[i]=bq; ak[i]=bk; av[i]=bv; }
        const float* w12 = W12 + j;
        const float* w13 = W13 + j;
        const float* w14 = W14 + j;
        #pragma unroll 2
        for (int kk = 0; kk < 2*D_; kk += 4) {
            const float wq0=__ldg(w12+(kk  )*D_), wq1=__ldg(w12+(kk+1)*D_),
                        wq2=__ldg(w12+(kk+2)*D_), wq3=__ldg(w12+(kk+3)*D_);
            const float wk0=__ldg(w13+(kk  )*D_), wk1=__ldg(w13+(kk+1)*D_),
                        wk2=__ldg(w13+(kk+2)*D_), wk3=__ldg(w13+(kk+3)*D_);
            const float wv0=__ldg(w14+(kk  )*D_), wv1=__ldg(w14+(kk+1)*D_),
                        wv2=__ldg(w14+(kk+2)*D_), wv3=__ldg(w14+(kk+3)*D_);
            #pragma unroll
            for (int tt = 0; tt < 12; tt++) {
                const float4 h = *reinterpret_cast<const float4*>(&sH[(t0+tt)*128 + kk]);
                aq[tt]=fmaf(h.x,wq0,aq[tt]); aq[tt]=fmaf(h.y,wq1,aq[tt]);
                aq[tt]=fmaf(h.z,wq2,aq[tt]); aq[tt]=fmaf(h.w,wq3,aq[tt]);
                ak[tt]=fmaf(h.x,wk0,ak[tt]); ak[tt]=fmaf(h.y,wk1,ak[tt]);
                ak[tt]=fmaf(h.z,wk2,ak[tt]); ak[tt]=fmaf(h.w,wk3,ak[tt]);
                av[tt]=fmaf(h.x,wv0,av[tt]); av[tt]=fmaf(h.y,wv1,av[tt]);
                av[tt]=fmaf(h.z,wv2,av[tt]); av[tt]=fmaf(h.w,wv3,av[tt]);
            }
        }
        #pragma unroll
        for (int tt = 0; tt < 12; tt++) {
            sQ[(t0+tt)*SP + j] = fmaxf(aq[tt], 0.f);
            sK[(t0+tt)*SP + j] = fmaxf(ak[tt], 0.f);
            sV[(t0+tt)*SP + j] = fmaxf(av[tt], 0.f);
        }
    }
    __syncthreads();

    // ---------------- Phase 2: per-head attention over T ----------------
    // warp = head. q,k non-negative (post-ReLU) => scores bounded, exp() safe
    // without max-subtraction: softmax = exp(s)/sum(exp(s)).
    {
        const int warp = tid >> 5;        // head 0..7
        const int lane = tid & 31;
        const int h2   = warp * 2;        // float4 offset within a row
        const float4* sQ4 = reinterpret_cast<const float4*>(sQ);
        const float4* sK4 = reinterpret_cast<const float4*>(sK);
        const float4* sV4 = reinterpret_cast<const float4*>(sV);
        const bool two = lane < 16;
        const int r0 = lane, r1 = lane + 32;

        const float4 qa0 = sQ4[r0*SP4 + h2];
        const float4 qb0 = sQ4[r0*SP4 + h2 + 1];
        float4 qa1 = make_float4(0.f,0.f,0.f,0.f), qb1 = qa1;
        if (two) { qa1 = sQ4[r1*SP4 + h2]; qb1 = sQ4[r1*SP4 + h2 + 1]; }

        float4 oa0 = make_float4(0.f,0.f,0.f,0.f), ob0 = oa0, oa1 = oa0, ob1 = oa0;
        float l0 = 0.f, l1 = 0.f;
        const float sc = 0.35355339059327373f;  // 1/sqrt(8)

        for (int p = 0; p < T_; p++) {
            const float4 ka = sK4[p*SP4 + h2], kb = sK4[p*SP4 + h2 + 1];
            const float4 va = sV4[p*SP4 + h2], vb = sV4[p*SP4 + h2 + 1];
            float s0;
            s0  = qa0.x*ka.x; s0 = fmaf(qa0.y,ka.y,s0); s0 = fmaf(qa0.z,ka.z,s0); s0 = fmaf(qa0.w,ka.w,s0);
            s0  = fmaf(qb0.x,kb.x,s0); s0 = fmaf(qb0.y,kb.y,s0); s0 = fmaf(qb0.z,kb.z,s0); s0 = fmaf(qb0.w,kb.w,s0);
            const float e0 = __expf(s0 * sc);
            l0 += e0;
            oa0.x = fmaf(e0,va.x,oa0.x); oa0.y = fmaf(e0,va.y,oa0.y);
            oa0.z = fmaf(e0,va.z,oa0.z); oa0.w = fmaf(e0,va.w,oa0.w);
            ob0.x = fmaf(e0,vb.x,ob0.x); ob0.y = fmaf(e0,vb.y,ob0.y);
            ob0.z = fmaf(e0,vb.z,ob0.z); ob0.w = fmaf(e0,vb.w,ob0.w);
            if (two) {
                float s1;
                s1  = qa1.x*ka.x; s1 = fmaf(qa1.y,ka.y,s1); s1 = fmaf(qa1.z,ka.z,s1); s1 = fmaf(qa1.w,ka.w,s1);
                s1  = fmaf(qb1.x,kb.x,s1); s1 = fmaf(qb1.y,kb.y,s1); s1 = fmaf(qb1.z,kb.z,s1); s1 = fmaf(qb1.w,kb.w,s1);
                const float e1 = __expf(s1 * sc);
                l1 += e1;
                oa1.x = fmaf(e1,va.x,oa1.x); oa1.y = fmaf(e1,va.y,oa1.y);
                oa1.z = fmaf(e1,va.z,oa1.z); oa1.w = fmaf(e1,va.w,oa1.w);
                ob1.x = fmaf(e1,vb.x,ob1.x); ob1.y = fmaf(e1,vb.y,ob1.y);
                ob1.z = fmaf(e1,vb.z,ob1.z); ob1.w = fmaf(e1,vb.w,ob1.w);
            }
        }
        float4* sO4 = reinterpret_cast<float4*>(sO);
        const float inv0 = 1.f / l0;
        sO4[r0*SP4 + h2]     = make_float4(oa0.x*inv0, oa0.y*inv0, oa0.z*inv0, oa0.w*inv0);
        sO4[r0*SP4 + h2 + 1] = make_float4(ob0.x*inv0, ob0.y*inv0, ob0.z*inv0, ob0.w*inv0);
        if (two) {
            const float inv1 = 1.f / l1;
            sO4[r1*SP4 + h2]     = make_float4(oa1.x*inv1, oa1.y*inv1, oa1.z*inv1, oa1.w*inv1);
            sO4[r1*SP4 + h2 + 1] = make_float4(ob1.x*inv1, ob1.y*inv1, ob1.z*inv1, ob1.w*inv1);
        }
    }
    __syncthreads();

    // ---------------- Phase 3a: mid = relu(attnOut @ W15 + b15) ----------------
    const int j  = tid & 63;
    const int g  = tid >> 6;
    const int t0 = g * 12;
    {
        float a[12];
        const float bb = __ldg(b15 + j);
        #pragma unroll
        for (int i = 0; i < 12; i++) a[i] = bb;
        const float* w = W15 + j;
        #pragma unroll 2
        for (int kk = 0; kk < D_; kk += 4) {
            const float w0=__ldg(w+(kk  )*D_), w1=__ldg(w+(kk+1)*D_),
                        w2=__ldg(w+(kk+2)*D_), w3=__ldg(w+(kk+3)*D_);
            #pragma unroll
            for (int tt = 0; tt < 12; tt++) {
                const float4 o = *reinterpret_cast<const float4*>(&sO[(t0+tt)*SP + kk]);
                a[tt]=fmaf(o.x,w0,a[tt]); a[tt]=fmaf(o.y,w1,a[tt]);
                a[tt]=fmaf(o.z,w2,a[tt]); a[tt]=fmaf(o.w,w3,a[tt]);
            }
        }
        __syncthreads();   // sT aliases sQ: make sure phase-2 readers are done (they are, after prior sync) and writes ordered
        #pragma unroll
        for (int tt = 0; tt < 12; tt++)
            sT[(t0+tt)*SP + j] = fmaxf(a[tt], 0.f);
    }
    __syncthreads();

    // ---------------- Phase 3b: out = mid @ W16 + b16 ----------------
    {
        float a[12];
        const float bb = __ldg(b16 + j);
        #pragma unroll
        for (int i = 0; i < 12; i++) a[i] = bb;
        const float* w = W16 + j;
        #pragma unroll 2
        for (int kk = 0; kk < D_; kk += 4) {
            const float w0=__ldg(w+(kk  )*D_), w1=__ldg(w+(kk+1)*D_),
                        w2=__ldg(w+(kk+2)*D_), w3=__ldg(w+(kk+3)*D_);
            #pragma unroll
            for (int tt = 0; tt < 12; tt++) {
                const float4 o = *reinterpret_cast<const float4*>(&sT[(t0+tt)*SP + kk]);
                a[tt]=fmaf(o.x,w0,a[tt]); a[tt]=fmaf(o.y,w1,a[tt]);
                a[tt]=fmaf(o.z,w2,a[tt]); a[tt]=fmaf(o.w,w3,a[tt]);
            }
        }
        const int obase = (b*T_*N_ + n) * D_ + j;
        #pragma unroll
        for (int tt = 0; tt < 12; tt++)
            out[obase + (t0+tt)*N_*D_] = a[tt];
    }
}

extern "C" void kernel_launch(void* const* d_in, const int* in_sizes, int n_in,
                              void* d_out, int out_size)
{
    (void)in_sizes; (void)n_in; (void)out_size;
    cudaFuncSetAttribute(fused_temporal_attn,
                         cudaFuncAttributeMaxDynamicSharedMemorySize, SMEM_BYTES);
    dim3 grid(N_, B_);
    fused_temporal_attn<<<grid, 256, SMEM_BYTES>>>(
        (const float*)d_in[0],  (const float*)d_in[1],
        (const float*)d_in[2],  (const float*)d_in[3],
        (const float*)d_in[4],  (const float*)d_in[5],
        (const float*)d_in[6],  (const float*)d_in[7],
        (const float*)d_in[8],  (const float*)d_in[9],
        (const float*)d_in[10], (const float*)d_in[11],
        (float*)d_out);
}